// round 11
// baseline (speedup 1.0000x reference)
#include <cuda_runtime.h>
#include <cstdint>

// Problem shape (fixed by the dataset)
#define B_BATCH 4
#define E_EDGES 320000
#define N_NODES 10000
#define F_FEAT  64

#define THREADS       256
#define CHUNK         128                          // edges per chunk
#define NSTAGES       3
#define CHUNKS_PER_B  (E_EDGES / CHUNK)            // 2500 (exact)
#define TOTAL_CHUNKS  (CHUNKS_PER_B * B_BATCH)     // 10000
#define NCTAS         296                          // 2 CTAs per SM

#define MSG_BYTES     (CHUNK * F_FEAT * 4)         // 32768
#define IDX_BYTES     (CHUNK * 4)                  // 512
#define STAGE_BYTES   (MSG_BYTES + IDX_BYTES)      // 33280
#define SMEM_DATA     (NSTAGES * STAGE_BYTES)      // 99840
#define SMEM_BYTES    (SMEM_DATA + NSTAGES * 16)   // + (full,empty) barrier pairs

__device__ __forceinline__ void mbar_init(uint32_t a, uint32_t cnt) {
    asm volatile("mbarrier.init.shared.b64 [%0], %1;" :: "r"(a), "r"(cnt) : "memory");
}
__device__ __forceinline__ void mbar_expect_tx(uint32_t a, uint32_t bytes) {
    asm volatile("mbarrier.arrive.expect_tx.shared.b64 _, [%0], %1;"
                 :: "r"(a), "r"(bytes) : "memory");
}
__device__ __forceinline__ void mbar_arrive(uint32_t a) {
    asm volatile("mbarrier.arrive.shared.b64 _, [%0];" :: "r"(a) : "memory");
}
__device__ __forceinline__ void mbar_wait(uint32_t a, uint32_t parity) {
    asm volatile(
        "{\n\t.reg .pred P;\n\t"
        "W_%=:\n\t"
        "mbarrier.try_wait.parity.acquire.cta.shared::cta.b64 P, [%0], %1, 0x989680;\n\t"
        "@P bra.uni D_%=;\n\t"
        "bra.uni W_%=;\n\t"
        "D_%=:\n\t}"
        :: "r"(a), "r"(parity) : "memory");
}
// Bulk copy global->shared through the TMA unit (NOT the LSU).
__device__ __forceinline__ void bulk_g2s(uint32_t dst, const void* src,
                                         uint32_t bytes, uint32_t mbar) {
    asm volatile(
        "cp.async.bulk.shared::cta.global.mbarrier::complete_tx::bytes [%0], [%1], %2, [%3];"
        :: "r"(dst), "l"(src), "r"(bytes), "r"(mbar) : "memory");
}

// Pipelined scatter-add: reads go through TMA (UBLKCP), reductions through the
// LSU. The two streams only meet at L2, so RED backpressure cannot throttle
// LDG issue (the failure mode of the plain-scatter and cp.async variants).
__global__ __launch_bounds__(THREADS, 2) void scatter_tma_kernel(
    const float4* __restrict__ msg,   // [B*E, 16] float4
    const int*    __restrict__ idx,   // [B*E]
    float*        __restrict__ out)   // [B, N, 64]
{
    extern __shared__ __align__(128) char smem[];
    const uint32_t sb  = (uint32_t)__cvta_generic_to_shared(smem);
    const uint32_t mbb = sb + SMEM_DATA;
    const int tid = threadIdx.x;

    if (tid == 0) {
#pragma unroll
        for (int s = 0; s < NSTAGES; ++s) {
            mbar_init(mbb + s * 16, 1);            // full: tx-based
            mbar_init(mbb + s * 16 + 8, THREADS);  // empty: all threads arrive
        }
    }
    __syncthreads();

    const bool leader = (tid == 0);
    int sp = 0, pp = 1;   // producer cursor (phase 1: first NSTAGES waits pass)
    int sc = 0, pc = 0;   // consumer cursor

    auto issue = [&](int c) {
        if (leader) {
            const uint32_t full  = mbb + sp * 16;
            const uint32_t empty = mbb + sp * 16 + 8;
            mbar_wait(empty, (uint32_t)pp);
            mbar_expect_tx(full, STAGE_BYTES);
            const uint32_t st = sb + sp * STAGE_BYTES;
            bulk_g2s(st,             msg + (long long)c * (CHUNK * 16), MSG_BYTES, full);
            bulk_g2s(st + MSG_BYTES, idx + (long long)c * CHUNK,        IDX_BYTES, full);
        }
        if (++sp == NSTAGES) { sp = 0; pp ^= 1; }
    };

    for (int k = 0;; ++k) {
        const int c = blockIdx.x + k * NCTAS;
        if (c >= TOTAL_CHUNKS) break;

        if (k == 0) {                     // prologue: fill stages 0,1
            issue(c);
            if (c + NCTAS < TOTAL_CHUNKS) issue(c + NCTAS);
        }
        const int cf = blockIdx.x + (k + 2) * NCTAS;
        if (cf < TOTAL_CHUNKS) issue(cf); // keep 3 stages in flight

        mbar_wait(mbb + sc * 16, (uint32_t)pc);    // full(stage sc), acquire

        const int b = c / CHUNKS_PER_B;            // chunks never straddle batches
        const float4* smsg = reinterpret_cast<const float4*>(smem + sc * STAGE_BYTES);
        const int*    sidx = reinterpret_cast<const int*>(smem + sc * STAGE_BYTES + MSG_BYTES);
        float* outb = out + (long long)b * N_NODES * F_FEAT;

#pragma unroll
        for (int i = 0; i < 8; ++i) {
            const int j    = tid + i * THREADS;    // 0..2047
            const float4 v = smsg[j];              // LDS.128, conflict-free
            const int node = sidx[j >> 4];         // broadcast in 16-lane groups
            float* dst = outb + node * F_FEAT + (j & 15) * 4;
            asm volatile(
                "red.global.add.v4.f32 [%0], {%1, %2, %3, %4};"
                :: "l"(dst), "f"(v.x), "f"(v.y), "f"(v.z), "f"(v.w)
                : "memory");
        }

        mbar_arrive(mbb + sc * 16 + 8);            // stage is free
        if (++sc == NSTAGES) { sc = 0; pc ^= 1; }
    }
}

extern "C" void kernel_launch(void* const* d_in, const int* in_sizes, int n_in,
                              void* d_out, int out_size) {
    const float4* msg = (const float4*)d_in[0];   // msg_vectors [B,E,F] f32
    const int*    idx = (const int*)d_in[1];      // start_indices [B,E] i32
    // d_in[2] = h_v, unused by the reference computation
    float* out = (float*)d_out;                   // [B,N,F] f32

    static bool attr_set = false;
    if (!attr_set) {
        cudaFuncSetAttribute(scatter_tma_kernel,
                             cudaFuncAttributeMaxDynamicSharedMemorySize, SMEM_BYTES);
        attr_set = true;
    }

    // 1) zero the output (harness poisons it with 0xAA)
    cudaMemsetAsync(out, 0, (size_t)out_size * sizeof(float), 0);

    // 2) TMA-fed pipelined scatter-add (2 CTAs/SM)
    scatter_tma_kernel<<<NCTAS, THREADS, SMEM_BYTES>>>(msg, idx, out);
}

// round 12
// speedup vs baseline: 1.0364x; 1.0364x over previous
#include <cuda_runtime.h>
#include <cstdint>

// Problem shape (fixed by the dataset)
#define B_BATCH 4
#define E_EDGES 320000
#define N_NODES 10000
#define F_FEAT  64
#define E_TOTAL (B_BATCH * E_EDGES)        // 1,280,000

#define WINDOW      1024                   // edges per CTA
#define RED_EDGES   896                    // handled by 8 RED warps
#define TMA_EDGES   128                    // handled by warp 8 via cp.reduce
#define NCTAS       (E_TOTAL / WINDOW)     // 1250 (exact)
#define THREADS     288                    // 9 warps

#define TMA_BYTES   (TMA_EDGES * 256)      // 32768

__device__ __forceinline__ void mbar_init(uint32_t a, uint32_t cnt) {
    asm volatile("mbarrier.init.shared.b64 [%0], %1;" :: "r"(a), "r"(cnt) : "memory");
}
__device__ __forceinline__ void mbar_expect_tx(uint32_t a, uint32_t bytes) {
    asm volatile("mbarrier.arrive.expect_tx.shared.b64 _, [%0], %1;"
                 :: "r"(a), "r"(bytes) : "memory");
}
__device__ __forceinline__ void mbar_wait(uint32_t a, uint32_t parity) {
    asm volatile(
        "{\n\t.reg .pred P;\n\t"
        "W_%=:\n\t"
        "mbarrier.try_wait.parity.acquire.cta.shared::cta.b64 P, [%0], %1, 0x989680;\n\t"
        "@P bra.uni D_%=;\n\t"
        "bra.uni W_%=;\n\t"
        "D_%=:\n\t}"
        :: "r"(a), "r"(parity) : "memory");
}
__device__ __forceinline__ void bulk_g2s(uint32_t dst, const void* src,
                                         uint32_t bytes, uint32_t mbar) {
    asm volatile(
        "cp.async.bulk.shared::cta.global.mbarrier::complete_tx::bytes [%0], [%1], %2, [%3];"
        :: "r"(dst), "l"(src), "r"(bytes), "r"(mbar) : "memory");
}
// 256B f32-add reduction smem -> global, executed by the TMA engine.
__device__ __forceinline__ void bulk_reduce_add(float* gdst, uint32_t ssrc, uint32_t bytes) {
    asm volatile(
        "cp.reduce.async.bulk.global.shared::cta.bulk_group.add.f32 [%0], [%1], %2;"
        :: "l"(gdst), "r"(ssrc), "r"(bytes) : "memory");
}

// Warp-specialized hybrid scatter-add.
// Warps 0-7: classic streaming LDG.128 + red.global.add.v4.f32 (the proven
// 70.5us path) on 7/8 of the edges. Warp 8: TMA bulk-load of the remaining
// 1/8, then per-edge 256B cp.reduce.async.bulk - reductions executed by the
// TMA engine instead of the SM RED path.
__global__ __launch_bounds__(THREADS) void scatter_hybrid_kernel(
    const float4* __restrict__ msg,   // [B*E, 16] float4 (batches contiguous)
    const int*    __restrict__ idx,   // [B*E]
    float*        __restrict__ out)   // [B, N, 64]
{
    __shared__ __align__(128) char sdata[TMA_BYTES];
    __shared__ __align__(8)  unsigned long long smbar;

    const int tid  = threadIdx.x;
    const int warp = tid >> 5;
    const int w0   = blockIdx.x * WINDOW;          // window base (fits in int)

    if (warp < 8) {
        // ---------------- RED path: 16 groups of 16 lanes, 56 edges each
        const int g  = tid >> 4;                   // 0..15
        const int f4 = tid & 15;
        const int eg0 = w0 + g * 56;

        for (int chunk = 0; chunk < 7; ++chunk) {
            const int e0 = eg0 + chunk * 8;

            const int4 ia = __ldg(reinterpret_cast<const int4*>(idx + e0));
            const int4 ib = __ldg(reinterpret_cast<const int4*>(idx + e0 + 4));
            const int node[8] = { ia.x, ia.y, ia.z, ia.w, ib.x, ib.y, ib.z, ib.w };

            float4 v[8];
#pragma unroll
            for (int u = 0; u < 8; ++u)
                v[u] = __ldcs(msg + (long long)(e0 + u) * 16 + f4);

#pragma unroll
            for (int u = 0; u < 8; ++u) {
                const int b = (e0 + u) / E_EDGES;  // const-div -> mul.hi
                float* dst = out + ((long long)b * N_NODES + node[u]) * F_FEAT + f4 * 4;
                asm volatile(
                    "red.global.add.v4.f32 [%0], {%1, %2, %3, %4};"
                    :: "l"(dst), "f"(v[u].x), "f"(v[u].y), "f"(v[u].z), "f"(v[u].w)
                    : "memory");
            }
        }
    } else {
        // ---------------- TMA path: edges [w0+896, w0+1024)
        const int lane = tid & 31;
        const uint32_t sb = (uint32_t)__cvta_generic_to_shared(sdata);
        const uint32_t mb = (uint32_t)__cvta_generic_to_shared(&smbar);

        if (lane == 0) {
            mbar_init(mb, 1);
            asm volatile("fence.proxy.async.shared::cta;" ::: "memory");
        }
        __syncwarp();
        if (lane == 0) {
            mbar_expect_tx(mb, TMA_BYTES);
            bulk_g2s(sb, msg + (long long)(w0 + RED_EDGES) * 16, TMA_BYTES, mb);
        }
        __syncwarp();
        mbar_wait(mb, 0);

#pragma unroll
        for (int r = 0; r < 4; ++r) {
            const int ew = RED_EDGES + lane + r * 32;   // window-local edge
            const int e  = w0 + ew;
            const int node = __ldg(idx + e);
            const int b = e / E_EDGES;
            float* dst = out + ((long long)b * N_NODES + node) * F_FEAT;
            bulk_reduce_add(dst, sb + (ew - RED_EDGES) * 256, 256);
        }
        asm volatile("cp.async.bulk.commit_group;" ::: "memory");
        asm volatile("cp.async.bulk.wait_group 0;" ::: "memory");
    }
}

extern "C" void kernel_launch(void* const* d_in, const int* in_sizes, int n_in,
                              void* d_out, int out_size) {
    const float4* msg = (const float4*)d_in[0];   // msg_vectors [B,E,F] f32
    const int*    idx = (const int*)d_in[1];      // start_indices [B,E] i32
    // d_in[2] = h_v, unused by the reference computation
    float* out = (float*)d_out;                   // [B,N,F] f32

    // 1) zero the output (harness poisons it with 0xAA)
    cudaMemsetAsync(out, 0, (size_t)out_size * sizeof(float), 0);

    // 2) hybrid scatter-add
    scatter_hybrid_kernel<<<NCTAS, THREADS>>>(msg, idx, out);
}